// round 7
// baseline (speedup 1.0000x reference)
#include <cuda_runtime.h>
#include <cuda_bf16.h>
#include <cuda_fp16.h>
#include <math.h>
#include <stdint.h>

#define N_NODES 100000
#define E_EDGES 3200000
#define F_IN    256
#define D_OUT   128

// ---------------- static scratch (no cudaMalloc allowed) ----------------
__device__ float g_u[F_IN];
__device__ float g_v[F_IN];
__device__ float g_sa1[N_NODES];
__device__ float g_sa2[N_NODES];
__device__ float g_vscale[N_NODES];
__device__ int   g_rowptr[N_NODES + 1];
__device__ short g_qval[(size_t)N_NODES * D_OUT];    // 25.6 MB int16 value, fits L2
__device__ __nv_bfloat16 g_Bhi[D_OUT * F_IN];        // 64 KB, [n][k]
__device__ __nv_bfloat16 g_Blo[D_OUT * F_IN];        // 64 KB

// ---------------- helpers ----------------
__device__ __forceinline__ void cvt_pair(float x, float y, uint32_t& hi, uint32_t& lo) {
    __nv_bfloat16 hx = __float2bfloat16_rn(x);
    __nv_bfloat16 hy = __float2bfloat16_rn(y);
    hi = (uint32_t)__bfloat16_as_ushort(hx) | ((uint32_t)__bfloat16_as_ushort(hy) << 16);
    __nv_bfloat16 lx = __float2bfloat16_rn(x - __bfloat162float(hx));
    __nv_bfloat16 ly = __float2bfloat16_rn(y - __bfloat162float(hy));
    lo = (uint32_t)__bfloat16_as_ushort(lx) | ((uint32_t)__bfloat16_as_ushort(ly) << 16);
}

__device__ __forceinline__ void mma16816(float* c, const uint32_t* a, uint32_t b0, uint32_t b1) {
    asm volatile(
        "mma.sync.aligned.m16n8k16.row.col.f32.bf16.bf16.f32 "
        "{%0,%1,%2,%3}, {%4,%5,%6,%7}, {%8,%9}, {%0,%1,%2,%3};"
        : "+f"(c[0]), "+f"(c[1]), "+f"(c[2]), "+f"(c[3])
        : "r"(a[0]), "r"(a[1]), "r"(a[2]), "r"(a[3]), "r"(b0), "r"(b1));
}

// ---------------- prep: uv (block 0) + B conversion ----------------
__global__ void prep_kernel(const float* __restrict__ kern,
                            const float* __restrict__ W1,
                            const float* __restrict__ w2,
                            const float* __restrict__ w3) {
    int idx = blockIdx.x * blockDim.x + threadIdx.x;
    if (idx < F_IN * D_OUT) {
        int k = idx >> 7;
        int n = idx & 127;
        float v = kern[k * D_OUT + n];
        __nv_bfloat16 h = __float2bfloat16_rn(v);
        __nv_bfloat16 l = __float2bfloat16_rn(v - __bfloat162float(h));
        g_Bhi[n * F_IN + k] = h;
        g_Blo[n * F_IN + k] = l;
    }
    if (blockIdx.x == 0) {
        int t = threadIdx.x;
        float su = 0.f, sv = 0.f;
        #pragma unroll 8
        for (int d = 0; d < D_OUT; d++) {
            float w = W1[t * D_OUT + d];
            su += w * w2[d];
            sv += w * w3[d];
        }
        g_u[t] = su;
        g_v[t] = sv;
    }
}

// ---------------- row_ptr by boundary scatter ----------------
__global__ void rowptr_kernel(const int* __restrict__ er) {
    int j = blockIdx.x * blockDim.x + threadIdx.x;
    if (j > E_EDGES) return;
    int hi = (j == E_EDGES) ? N_NODES : er[j];
    int lo = (j == 0) ? -1 : er[j - 1];
    for (int i = lo + 1; i <= hi; i++) g_rowptr[i] = j;
}

// ---------------- HMMA GEMM: 512 threads, 16 warps, double-buffered A ----------------
#define SPADW 132
#define APADW 20
#define ABUF_W 5120                        // hi+lo per buffer (2*128*20)
#define SM_BHI_W 0
#define SM_BLO_W (128 * SPADW)             // 16896
#define SM_A_W   (2 * 128 * SPADW)         // 33792
#define SM_U_W   (SM_A_W + 2 * ABUF_W)     // 44032
#define SM_V_W   (SM_U_W + 256)
#define SMEM_WORDS (SM_V_W + 256)          // 44544
#define SMEM_BYTES (SMEM_WORDS * 4)        // 178176 B
#define CPADW 132
#define SM_PMAX_W SM_BLO_W                 // reuse B-lo region (512 floats)

__global__ void __launch_bounds__(512, 1)
mma_gemm(const float* __restrict__ A, short* __restrict__ Q,
         const float* __restrict__ b2, const float* __restrict__ b3, int M) {
    extern __shared__ uint32_t sm[];
    int tid = threadIdx.x;

    // preload B (padded) and u/v
    {
        const uint4* bh = (const uint4*)g_Bhi;
        const uint4* bl = (const uint4*)g_Blo;
        #pragma unroll
        for (int r = 0; r < 8; r++) {
            int i = tid + r * 512;            // 0..4095 uint4
            int n = i >> 5, w = i & 31;
            *(uint4*)(sm + SM_BHI_W + n * SPADW + w * 4) = bh[i];
            *(uint4*)(sm + SM_BLO_W + n * SPADW + w * 4) = bl[i];
        }
        if (tid < 256) {
            sm[SM_U_W + tid] = ((const uint32_t*)g_u)[tid];
            sm[SM_V_W + tid] = ((const uint32_t*)g_v)[tid];
        }
    }
    __syncthreads();

    const float* sU = (const float*)(sm + SM_U_W);
    const float* sV = (const float*)(sm + SM_V_W);

    int wid = tid >> 5, lane = tid & 31;
    int wr = wid >> 2, wc = wid & 3;       // warp grid 4 x 4
    int lg = lane >> 2, lq = lane & 3;
    long base = (long)blockIdx.x * 128;
    int nbase = wc * 32;
    int kq = lq * 2;

    int srow = tid >> 2;                   // 0..127  (one row per thread)
    int skk  = (tid & 3) * 8;              // 0,8,16,24

    float acc[2][4][4];
    #pragma unroll
    for (int i = 0; i < 2; i++)
        #pragma unroll
        for (int j = 0; j < 4; j++)
            #pragma unroll
            for (int q = 0; q < 4; q++) acc[i][j][q] = 0.f;

    float s1 = 0.f, s2 = 0.f;
    float4 areg0, areg1;
    long my_grow = base + srow;
    if (my_grow >= M) my_grow = M - 1;
    const float* aptr = A + my_grow * F_IN + skk;

    auto load_chunk = [&](int k0) {
        areg0 = *(const float4*)(aptr + k0);
        areg1 = *(const float4*)(aptr + k0 + 4);
    };
    auto store_chunk = [&](int k0, int bb) {
        uint32_t* ahi = sm + SM_A_W + bb * ABUF_W;
        uint32_t* alo = ahi + 2560;
        const float* u = sU + k0 + skk;
        const float* v = sV + k0 + skk;
        s1 += areg0.x * u[0] + areg0.y * u[1] + areg0.z * u[2] + areg0.w * u[3]
            + areg1.x * u[4] + areg1.y * u[5] + areg1.z * u[6] + areg1.w * u[7];
        s2 += areg0.x * v[0] + areg0.y * v[1] + areg0.z * v[2] + areg0.w * v[3]
            + areg1.x * v[4] + areg1.y * v[5] + areg1.z * v[6] + areg1.w * v[7];
        uint32_t h0, l0, h1, l1, h2, l2, h3, l3;
        cvt_pair(areg0.x, areg0.y, h0, l0);
        cvt_pair(areg0.z, areg0.w, h1, l1);
        cvt_pair(areg1.x, areg1.y, h2, l2);
        cvt_pair(areg1.z, areg1.w, h3, l3);
        int wb = srow * APADW + (skk >> 1);
        *(uint2*)(ahi + wb)     = make_uint2(h0, h1);
        *(uint2*)(ahi + wb + 2) = make_uint2(h2, h3);
        *(uint2*)(alo + wb)     = make_uint2(l0, l1);
        *(uint2*)(alo + wb + 2) = make_uint2(l2, l3);
    };

    load_chunk(0);
    store_chunk(0, 0);
    __syncthreads();

    #pragma unroll 1
    for (int c = 0; c < 8; ++c) {
        if (c < 7) load_chunk((c + 1) * 32);    // LDGs in flight during MMA

        const uint32_t* ahi = sm + SM_A_W + (c & 1) * ABUF_W;
        const uint32_t* alo = ahi + 2560;
        #pragma unroll
        for (int ksi = 0; ksi < 2; ++ksi) {
            uint32_t ah[2][4], al[2][4];
            #pragma unroll
            for (int mt = 0; mt < 2; mt++) {
                int r0 = wr * 32 + mt * 16 + lg;
                int w0 = r0 * APADW + ksi * 8 + lq;
                int w1 = (r0 + 8) * APADW + ksi * 8 + lq;
                ah[mt][0] = ahi[w0];
                ah[mt][1] = ahi[w1];
                ah[mt][2] = ahi[w0 + 4];
                ah[mt][3] = ahi[w1 + 4];
                al[mt][0] = alo[w0];
                al[mt][1] = alo[w1];
                al[mt][2] = alo[w0 + 4];
                al[mt][3] = alo[w1 + 4];
            }
            uint32_t bh0[4], bh1[4], bl0[4], bl1[4];
            int kglob = c * 32 + ksi * 16;
            #pragma unroll
            for (int nt = 0; nt < 4; nt++) {
                int n0 = nbase + nt * 8 + lg;
                uint32_t off = (uint32_t)n0 * SPADW + (uint32_t)((kglob + kq) >> 1);
                bh0[nt] = sm[SM_BHI_W + off];
                bh1[nt] = sm[SM_BHI_W + off + 4];
                bl0[nt] = sm[SM_BLO_W + off];
                bl1[nt] = sm[SM_BLO_W + off + 4];
            }
            #pragma unroll
            for (int mt = 0; mt < 2; mt++)
                #pragma unroll
                for (int nt = 0; nt < 4; nt++)
                    mma16816(acc[mt][nt], ah[mt], bh0[nt], bh1[nt]);
            #pragma unroll
            for (int mt = 0; mt < 2; mt++)
                #pragma unroll
                for (int nt = 0; nt < 4; nt++)
                    mma16816(acc[mt][nt], ah[mt], bl0[nt], bl1[nt]);
            #pragma unroll
            for (int mt = 0; mt < 2; mt++)
                #pragma unroll
                for (int nt = 0; nt < 4; nt++)
                    mma16816(acc[mt][nt], al[mt], bh0[nt], bh1[nt]);
        }

        if (c < 7) store_chunk((c + 1) * 32, (c + 1) & 1);
        __syncthreads();
    }

    // sa reduce over the 4 staging threads per row (consecutive lanes)
    {
        float a1 = s1, a2 = s2;
        a1 += __shfl_xor_sync(0xffffffffu, a1, 1);
        a2 += __shfl_xor_sync(0xffffffffu, a2, 1);
        a1 += __shfl_xor_sync(0xffffffffu, a1, 2);
        a2 += __shfl_xor_sync(0xffffffffu, a2, 2);
        if ((tid & 3) == 0) {
            long grow = base + srow;
            if (grow < M) {
                g_sa1[grow] = a1 + b2[0];
                g_sa2[grow] = a2 + b3[0];
            }
        }
    }

    // epilogue: dump acc to smem fp32 (reuse B-hi region)
    float* cs = (float*)sm;
    #pragma unroll
    for (int mt = 0; mt < 2; mt++) {
        int r0 = wr * 32 + mt * 16 + lg;
        #pragma unroll
        for (int nt = 0; nt < 4; nt++) {
            int col = nbase + nt * 8 + kq;
            *(float2*)(cs + r0 * CPADW + col) =
                make_float2(acc[mt][nt][0], acc[mt][nt][1]);
            *(float2*)(cs + (r0 + 8) * CPADW + col) =
                make_float2(acc[mt][nt][2], acc[mt][nt][3]);
        }
    }
    __syncthreads();

    // per-row absmax (4 threads per row), scale, int16 quantize
    {
        int row = tid >> 2, quarter = tid & 3;
        const float* cr = cs + row * CPADW + quarter * 32;
        float mx = 0.f;
        #pragma unroll 8
        for (int j = 0; j < 32; j++) mx = fmaxf(mx, fabsf(cr[j]));
        ((float*)(sm + SM_PMAX_W))[tid] = mx;
        __syncthreads();
        const float* pm = (const float*)(sm + SM_PMAX_W) + row * 4;
        float rmx = fmaxf(fmaxf(pm[0], pm[1]), fmaxf(pm[2], pm[3]));
        rmx = fmaxf(rmx, 1e-30f);
        long grow = base + row;
        if (quarter == 0 && grow < M) g_vscale[grow] = rmx * (1.0f / 32767.0f);
        float inv = 32767.0f / rmx;
        if (grow < M) {
            uint4* dst = (uint4*)(Q + (grow << 7) + quarter * 32);
            #pragma unroll
            for (int b8 = 0; b8 < 4; b8++) {
                short sv[8];
                #pragma unroll
                for (int j = 0; j < 8; j++)
                    sv[j] = (short)__float2int_rn(cr[b8 * 8 + j] * inv);
                dst[b8] = *(uint4*)sv;
            }
        }
    }
}

// ---------------- fused softmax + SpMM ----------------
// Gather unrolled x8 (front-batched LDGs) with dual accumulators.
__device__ __forceinline__ void gather8(const float2* __restrict__ wc, int t, int lane,
                                        float4& a0, float4& a1) {
    float w[8];
    int cj[8];
    #pragma unroll
    for (int q = 0; q < 8; q++) {
        float2 e = wc[t + q];
        w[q] = e.x;
        cj[q] = __float_as_int(e.y);
    }
    int2 raw[8];
    #pragma unroll
    for (int q = 0; q < 8; q++)
        raw[q] = *(const int2*)(g_qval + ((size_t)cj[q] << 7) + lane * 4);
    #pragma unroll
    for (int q = 0; q < 8; q++) {
        short2 p0 = *reinterpret_cast<short2*>(&raw[q].x);
        short2 p1 = *reinterpret_cast<short2*>(&raw[q].y);
        float4& a = (q & 1) ? a1 : a0;
        a.x += w[q] * (float)p0.x;
        a.y += w[q] * (float)p0.y;
        a.z += w[q] * (float)p1.x;
        a.w += w[q] * (float)p1.y;
    }
}

__global__ __launch_bounds__(256) void spmm_kernel(const float* __restrict__ adj,
                                                   const int* __restrict__ col,
                                                   const float* __restrict__ bias,
                                                   float* __restrict__ out) {
    __shared__ float2 s_wc[8][32];
    int warp = threadIdx.x >> 5, lane = threadIdx.x & 31;
    int row = blockIdx.x * 8 + warp;
    if (row >= N_NODES) return;

    int start = g_rowptr[row];
    int end   = g_rowptr[row + 1];
    int deg   = end - start;
    const float4 bv = *(const float4*)(bias + (size_t)row * D_OUT + lane * 4);

    if (deg <= 0) {
        *(float4*)(out + (size_t)row * D_OUT + lane * 4) = bv;
        return;
    }

    float sa1r = g_sa1[row];
    float4 a0 = make_float4(0.f, 0.f, 0.f, 0.f);
    float4 a1 = make_float4(0.f, 0.f, 0.f, 0.f);
    float dsum = 0.f;
    float2* wc = s_wc[warp];

    if (deg <= 32) {
        // single-batch fast path
        int j = start + lane;
        bool v = j < end;
        int c = v ? col[j] : col[start];
        float a = v ? adj[j] : 0.f;
        float e = a * (sa1r + g_sa2[c]);
        e = e > 0.f ? e : 0.2f * e;
        float m = v ? e : -INFINITY;
        #pragma unroll
        for (int o = 16; o; o >>= 1)
            m = fmaxf(m, __shfl_xor_sync(0xffffffffu, m, o));
        float ex = v ? __expf(e - m) : 0.f;
        dsum = ex;
        wc[lane] = make_float2(ex * g_vscale[c], __int_as_float(c));
        __syncwarp();
        int cnt8 = (deg + 7) & ~7;
        for (int t = 0; t < cnt8; t += 8) gather8(wc, t, lane, a0, a1);
    } else {
        // pass 1: segment max
        float m = -INFINITY;
        for (int j = start + lane; j < end; j += 32) {
            float a = adj[j];
            int   c = col[j];
            float e = a * (sa1r + g_sa2[c]);
            e = e > 0.f ? e : 0.2f * e;
            m = fmaxf(m, e);
        }
        #pragma unroll
        for (int o = 16; o; o >>= 1)
            m = fmaxf(m, __shfl_xor_sync(0xffffffffu, m, o));

        // pass 2: staged weights + unrolled gather
        for (int b = start; b < end; b += 32) {
            int j = b + lane;
            bool v = j < end;
            int c = v ? col[j] : col[start];
            float a = v ? adj[j] : 0.f;
            float e = a * (sa1r + g_sa2[c]);
            e = e > 0.f ? e : 0.2f * e;
            float ex = v ? __expf(e - m) : 0.f;
            dsum += ex;
            wc[lane] = make_float2(ex * g_vscale[c], __int_as_float(c));
            __syncwarp();
            int cnt8 = (min(32, end - b) + 7) & ~7;
            for (int t = 0; t < cnt8; t += 8) gather8(wc, t, lane, a0, a1);
            __syncwarp();
        }
    }

    float4 acc = make_float4(a0.x + a1.x, a0.y + a1.y, a0.z + a1.z, a0.w + a1.w);

    #pragma unroll
    for (int o = 16; o; o >>= 1)
        dsum += __shfl_xor_sync(0xffffffffu, dsum, o);
    if (dsum <= 0.f) dsum = 1.0f;
    float inv = 1.0f / dsum;

    float4 ov;
    ov.x = acc.x * inv + bv.x;
    ov.y = acc.y * inv + bv.y;
    ov.z = acc.z * inv + bv.z;
    ov.w = acc.w * inv + bv.w;
    *(float4*)(out + (size_t)row * D_OUT + lane * 4) = ov;
}

// ---------------- launch ----------------
extern "C" void kernel_launch(void* const* d_in, const int* in_sizes, int n_in,
                              void* d_out, int out_size) {
    const float* x        = (const float*)d_in[0];
    const float* adj_val  = (const float*)d_in[1];
    const float* W1       = (const float*)d_in[2];
    const float* w2       = (const float*)d_in[3];
    const float* b2       = (const float*)d_in[4];
    const float* w3       = (const float*)d_in[5];
    const float* b3       = (const float*)d_in[6];
    const float* kern     = (const float*)d_in[7];
    const float* bias     = (const float*)d_in[8];
    const int*   edge_row = (const int*)d_in[9];
    const int*   edge_col = (const int*)d_in[10];
    float* out = (float*)d_out;

    short* qval;
    cudaGetSymbolAddress((void**)&qval, g_qval);

    cudaFuncSetAttribute(mma_gemm, cudaFuncAttributeMaxDynamicSharedMemorySize, SMEM_BYTES);

    prep_kernel<<<(F_IN * D_OUT + 255) / 256, 256>>>(kern, W1, w2, w3);
    rowptr_kernel<<<(E_EDGES + 1 + 255) / 256, 256>>>(edge_row);
    mma_gemm<<<(N_NODES + 127) / 128, 512, SMEM_BYTES>>>(x, qval, b2, b3, N_NODES);
    spmm_kernel<<<(N_NODES + 7) / 8, 256>>>(adj_val, edge_col, bias, out);
}

// round 8
// speedup vs baseline: 1.1113x; 1.1113x over previous
#include <cuda_runtime.h>
#include <cuda_bf16.h>
#include <cuda_fp16.h>
#include <math.h>
#include <stdint.h>

#define N_NODES 100000
#define E_EDGES 3200000
#define F_IN    256
#define D_OUT   128

// ---------------- static scratch (no cudaMalloc allowed) ----------------
__device__ float g_u[F_IN];
__device__ float g_v[F_IN];
__device__ float g_sa1[N_NODES];
__device__ float g_sa2[N_NODES];
__device__ float g_vscale[N_NODES];
__device__ int   g_rowptr[N_NODES + 1];
__device__ short g_qval[(size_t)N_NODES * D_OUT];    // 25.6 MB int16 value, fits L2
__device__ __nv_bfloat16 g_Bhi[D_OUT * F_IN];        // 64 KB, [n][k]
__device__ __nv_bfloat16 g_Blo[D_OUT * F_IN];        // 64 KB

// ---------------- helpers ----------------
__device__ __forceinline__ void cvt_pair(float x, float y, uint32_t& hi, uint32_t& lo) {
    __nv_bfloat16 hx = __float2bfloat16_rn(x);
    __nv_bfloat16 hy = __float2bfloat16_rn(y);
    hi = (uint32_t)__bfloat16_as_ushort(hx) | ((uint32_t)__bfloat16_as_ushort(hy) << 16);
    __nv_bfloat16 lx = __float2bfloat16_rn(x - __bfloat162float(hx));
    __nv_bfloat16 ly = __float2bfloat16_rn(y - __bfloat162float(hy));
    lo = (uint32_t)__bfloat16_as_ushort(lx) | ((uint32_t)__bfloat16_as_ushort(ly) << 16);
}

__device__ __forceinline__ void mma16816(float* c, const uint32_t* a, uint32_t b0, uint32_t b1) {
    asm volatile(
        "mma.sync.aligned.m16n8k16.row.col.f32.bf16.bf16.f32 "
        "{%0,%1,%2,%3}, {%4,%5,%6,%7}, {%8,%9}, {%0,%1,%2,%3};"
        : "+f"(c[0]), "+f"(c[1]), "+f"(c[2]), "+f"(c[3])
        : "r"(a[0]), "r"(a[1]), "r"(a[2]), "r"(a[3]), "r"(b0), "r"(b1));
}

// ---------------- prep: uv (block 0) + B conversion ----------------
__global__ void prep_kernel(const float* __restrict__ kern,
                            const float* __restrict__ W1,
                            const float* __restrict__ w2,
                            const float* __restrict__ w3) {
    int idx = blockIdx.x * blockDim.x + threadIdx.x;
    if (idx < F_IN * D_OUT) {
        int k = idx >> 7;
        int n = idx & 127;
        float v = kern[k * D_OUT + n];
        __nv_bfloat16 h = __float2bfloat16_rn(v);
        __nv_bfloat16 l = __float2bfloat16_rn(v - __bfloat162float(h));
        g_Bhi[n * F_IN + k] = h;
        g_Blo[n * F_IN + k] = l;
    }
    if (blockIdx.x == 0) {
        int t = threadIdx.x;
        float su = 0.f, sv = 0.f;
        #pragma unroll 8
        for (int d = 0; d < D_OUT; d++) {
            float w = W1[t * D_OUT + d];
            su += w * w2[d];
            sv += w * w3[d];
        }
        g_u[t] = su;
        g_v[t] = sv;
    }
}

// ---------------- row_ptr by boundary scatter ----------------
__global__ void rowptr_kernel(const int* __restrict__ er) {
    int j = blockIdx.x * blockDim.x + threadIdx.x;
    if (j > E_EDGES) return;
    int hi = (j == E_EDGES) ? N_NODES : er[j];
    int lo = (j == 0) ? -1 : er[j - 1];
    for (int i = lo + 1; i <= hi; i++) g_rowptr[i] = j;
}

// ---------------- HMMA GEMM (R6 config: 256 thr, double-buffered A) ----------------
#define SPADW 132
#define APADW 20
#define ABUF_W 5120
#define SM_BHI_W 0
#define SM_BLO_W (128 * SPADW)
#define SM_A_W   (2 * 128 * SPADW)
#define SM_U_W   (SM_A_W + 2 * ABUF_W)
#define SM_V_W   (SM_U_W + 256)
#define SMEM_WORDS (SM_V_W + 256)
#define SMEM_BYTES (SMEM_WORDS * 4)        // 178176 B
#define CPADW 132
#define SM_PMAX_W SM_BLO_W

__global__ void __launch_bounds__(256, 1)
mma_gemm(const float* __restrict__ A, short* __restrict__ Q,
         const float* __restrict__ b2, const float* __restrict__ b3, int M) {
    extern __shared__ uint32_t sm[];
    int tid = threadIdx.x;

    {
        const uint4* bh = (const uint4*)g_Bhi;
        const uint4* bl = (const uint4*)g_Blo;
        #pragma unroll
        for (int r = 0; r < 16; r++) {
            int i = tid + r * 256;
            int n = i >> 5, w = i & 31;
            *(uint4*)(sm + SM_BHI_W + n * SPADW + w * 4) = bh[i];
            *(uint4*)(sm + SM_BLO_W + n * SPADW + w * 4) = bl[i];
        }
        sm[SM_U_W + tid] = ((const uint32_t*)g_u)[tid];
        sm[SM_V_W + tid] = ((const uint32_t*)g_v)[tid];
    }
    __syncthreads();

    const float* sU = (const float*)(sm + SM_U_W);
    const float* sV = (const float*)(sm + SM_V_W);

    int wid = tid >> 5, lane = tid & 31;
    int wr = wid >> 2, wc = wid & 3;
    int lg = lane >> 2, lq = lane & 3;
    long base = (long)blockIdx.x * 128;
    int nbase = wc * 32;
    int kq = lq * 2;

    int srow_g = tid >> 3;
    int skk = (tid & 7) * 4;

    float acc[4][4][4];
    #pragma unroll
    for (int i = 0; i < 4; i++)
        #pragma unroll
        for (int j = 0; j < 4; j++)
            #pragma unroll
            for (int q = 0; q < 4; q++) acc[i][j][q] = 0.f;

    float s1[4] = {0.f, 0.f, 0.f, 0.f}, s2[4] = {0.f, 0.f, 0.f, 0.f};
    float4 areg[4];

    auto load_chunk = [&](int k0) {
        #pragma unroll
        for (int it = 0; it < 4; ++it) {
            int row = it * 32 + srow_g;
            long grow = base + row;
            if (grow >= M) grow = M - 1;
            areg[it] = *(const float4*)(A + grow * F_IN + k0 + skk);
        }
    };
    auto store_chunk = [&](int k0, int bb) {
        uint32_t* ahi = sm + SM_A_W + bb * ABUF_W;
        uint32_t* alo = ahi + 2560;
        float u0 = sU[k0 + skk], u1 = sU[k0 + skk + 1],
              u2 = sU[k0 + skk + 2], u3 = sU[k0 + skk + 3];
        float v0 = sV[k0 + skk], v1 = sV[k0 + skk + 1],
              v2 = sV[k0 + skk + 2], v3 = sV[k0 + skk + 3];
        #pragma unroll
        for (int it = 0; it < 4; ++it) {
            int row = it * 32 + srow_g;
            float4 a = areg[it];
            s1[it] += a.x * u0 + a.y * u1 + a.z * u2 + a.w * u3;
            s2[it] += a.x * v0 + a.y * v1 + a.z * v2 + a.w * v3;
            uint32_t h0, l0, h1, l1;
            cvt_pair(a.x, a.y, h0, l0);
            cvt_pair(a.z, a.w, h1, l1);
            int wbase = row * APADW + (skk >> 1);
            *(uint2*)(ahi + wbase) = make_uint2(h0, h1);
            *(uint2*)(alo + wbase) = make_uint2(l0, l1);
        }
    };

    load_chunk(0);
    store_chunk(0, 0);
    __syncthreads();

    #pragma unroll 1
    for (int c = 0; c < 8; ++c) {
        if (c < 7) load_chunk((c + 1) * 32);

        const uint32_t* ahi = sm + SM_A_W + (c & 1) * ABUF_W;
        const uint32_t* alo = ahi + 2560;
        #pragma unroll
        for (int ksi = 0; ksi < 2; ++ksi) {
            uint32_t ah[4][4], al[4][4];
            #pragma unroll
            for (int mt = 0; mt < 4; mt++) {
                int r0 = wr * 64 + mt * 16 + lg;
                int w0 = r0 * APADW + ksi * 8 + lq;
                int w1 = (r0 + 8) * APADW + ksi * 8 + lq;
                ah[mt][0] = ahi[w0];
                ah[mt][1] = ahi[w1];
                ah[mt][2] = ahi[w0 + 4];
                ah[mt][3] = ahi[w1 + 4];
                al[mt][0] = alo[w0];
                al[mt][1] = alo[w1];
                al[mt][2] = alo[w0 + 4];
                al[mt][3] = alo[w1 + 4];
            }
            uint32_t bh0[4], bh1[4], bl0[4], bl1[4];
            int kglob = c * 32 + ksi * 16;
            #pragma unroll
            for (int nt = 0; nt < 4; nt++) {
                int n0 = nbase + nt * 8 + lg;
                uint32_t off = (uint32_t)n0 * SPADW + (uint32_t)((kglob + kq) >> 1);
                bh0[nt] = sm[SM_BHI_W + off];
                bh1[nt] = sm[SM_BHI_W + off + 4];
                bl0[nt] = sm[SM_BLO_W + off];
                bl1[nt] = sm[SM_BLO_W + off + 4];
            }
            #pragma unroll
            for (int mt = 0; mt < 4; mt++)
                #pragma unroll
                for (int nt = 0; nt < 4; nt++)
                    mma16816(acc[mt][nt], ah[mt], bh0[nt], bh1[nt]);
            #pragma unroll
            for (int mt = 0; mt < 4; mt++)
                #pragma unroll
                for (int nt = 0; nt < 4; nt++)
                    mma16816(acc[mt][nt], ah[mt], bl0[nt], bl1[nt]);
            #pragma unroll
            for (int mt = 0; mt < 4; mt++)
                #pragma unroll
                for (int nt = 0; nt < 4; nt++)
                    mma16816(acc[mt][nt], al[mt], bh0[nt], bh1[nt]);
        }

        if (c < 7) store_chunk((c + 1) * 32, (c + 1) & 1);
        __syncthreads();
    }

    {
        float bb2 = b2[0], bb3 = b3[0];
        #pragma unroll
        for (int it = 0; it < 4; ++it) {
            float a1 = s1[it], a2 = s2[it];
            #pragma unroll
            for (int o = 4; o; o >>= 1) {
                a1 += __shfl_xor_sync(0xffffffffu, a1, o);
                a2 += __shfl_xor_sync(0xffffffffu, a2, o);
            }
            if ((tid & 7) == 0) {
                long grow = base + it * 32 + srow_g;
                if (grow < M) {
                    g_sa1[grow] = a1 + bb2;
                    g_sa2[grow] = a2 + bb3;
                }
            }
        }
    }

    float* cs = (float*)sm;
    #pragma unroll
    for (int mt = 0; mt < 4; mt++) {
        int r0 = wr * 64 + mt * 16 + lg;
        #pragma unroll
        for (int nt = 0; nt < 4; nt++) {
            int col = nbase + nt * 8 + kq;
            *(float2*)(cs + r0 * CPADW + col) =
                make_float2(acc[mt][nt][0], acc[mt][nt][1]);
            *(float2*)(cs + (r0 + 8) * CPADW + col) =
                make_float2(acc[mt][nt][2], acc[mt][nt][3]);
        }
    }
    __syncthreads();

    {
        int row = tid >> 1, half = tid & 1;
        const float* cr = cs + row * CPADW + half * 64;
        float mx = 0.f;
        #pragma unroll 16
        for (int j = 0; j < 64; j++) mx = fmaxf(mx, fabsf(cr[j]));
        ((float*)(sm + SM_PMAX_W))[tid] = mx;
        __syncthreads();
        float rmx = fmaxf(((float*)(sm + SM_PMAX_W))[row * 2],
                          ((float*)(sm + SM_PMAX_W))[row * 2 + 1]);
        rmx = fmaxf(rmx, 1e-30f);
        long grow = base + row;
        if (half == 0 && grow < M) g_vscale[grow] = rmx * (1.0f / 32767.0f);
        float inv = 32767.0f / rmx;
        if (grow < M) {
            uint4* dst = (uint4*)(Q + (grow << 7) + half * 64);
            #pragma unroll
            for (int b8 = 0; b8 < 8; b8++) {
                short sv[8];
                #pragma unroll
                for (int j = 0; j < 8; j++)
                    sv[j] = (short)__float2int_rn(cr[b8 * 8 + j] * inv);
                dst[b8] = *(uint4*)sv;
            }
        }
    }
}

// ---------------- fused softmax + SpMM: paired-edge LDG.128 gather ----------------
// Lanes 0-15 take even edges, 16-31 odd edges. Each lane loads int4 (8 int16 cols).
// One LDG.128 instruction = 512 B = 2 full edges. Final shfl 16-merge combines halves.
__device__ __forceinline__ void gather8_pair(const float2* __restrict__ wc, int t,
                                             int half, int sublane, float* accp) {
    int4 raw[4];
    float w[4];
    #pragma unroll
    for (int q = 0; q < 4; q++) {
        float2 e = wc[t + 2 * q + half];
        w[q] = e.x;
        int cj = __float_as_int(e.y);
        raw[q] = *(const int4*)(g_qval + ((size_t)cj << 7) + sublane * 8);
    }
    #pragma unroll
    for (int q = 0; q < 4; q++) {
        short2 p0 = *reinterpret_cast<short2*>(&raw[q].x);
        short2 p1 = *reinterpret_cast<short2*>(&raw[q].y);
        short2 p2 = *reinterpret_cast<short2*>(&raw[q].z);
        short2 p3 = *reinterpret_cast<short2*>(&raw[q].w);
        accp[0] += w[q] * (float)p0.x;
        accp[1] += w[q] * (float)p0.y;
        accp[2] += w[q] * (float)p1.x;
        accp[3] += w[q] * (float)p1.y;
        accp[4] += w[q] * (float)p2.x;
        accp[5] += w[q] * (float)p2.y;
        accp[6] += w[q] * (float)p3.x;
        accp[7] += w[q] * (float)p3.y;
    }
}

__global__ __launch_bounds__(256) void spmm_kernel(const float* __restrict__ adj,
                                                   const int* __restrict__ col,
                                                   const float* __restrict__ bias,
                                                   float* __restrict__ out) {
    __shared__ float2 s_wc[8][32];
    int warp = threadIdx.x >> 5, lane = threadIdx.x & 31;
    int row = blockIdx.x * 8 + warp;
    if (row >= N_NODES) return;

    int start = g_rowptr[row];
    int end   = g_rowptr[row + 1];
    int deg   = end - start;
    int half = lane >> 4, sublane = lane & 15;

    if (deg <= 0) {
        if (half == 0) {
            const float4* bp = (const float4*)(bias + (size_t)row * D_OUT + sublane * 8);
            float4* op = (float4*)(out + (size_t)row * D_OUT + sublane * 8);
            op[0] = bp[0];
            op[1] = bp[1];
        }
        return;
    }

    float sa1r = g_sa1[row];
    float accp[8];
    #pragma unroll
    for (int i = 0; i < 8; i++) accp[i] = 0.f;
    float dsum = 0.f;
    float2* wcp = s_wc[warp];

    if (deg <= 32) {
        // single-batch fast path
        int j = start + lane;
        bool v = j < end;
        int c = v ? col[j] : col[start];
        float a = v ? adj[j] : 0.f;
        float e = a * (sa1r + g_sa2[c]);
        e = e > 0.f ? e : 0.2f * e;
        float m = v ? e : -INFINITY;
        #pragma unroll
        for (int o = 16; o; o >>= 1)
            m = fmaxf(m, __shfl_xor_sync(0xffffffffu, m, o));
        float ex = v ? __expf(e - m) : 0.f;
        dsum = ex;
        wcp[lane] = make_float2(ex * g_vscale[c], __int_as_float(c));
        __syncwarp();
        int cnt8 = (deg + 7) & ~7;
        for (int t = 0; t < cnt8; t += 8)
            gather8_pair(wcp, t, half, sublane, accp);
    } else {
        // pass 1: segment max
        float m = -INFINITY;
        for (int j = start + lane; j < end; j += 32) {
            float a = adj[j];
            int   c = col[j];
            float e = a * (sa1r + g_sa2[c]);
            e = e > 0.f ? e : 0.2f * e;
            m = fmaxf(m, e);
        }
        #pragma unroll
        for (int o = 16; o; o >>= 1)
            m = fmaxf(m, __shfl_xor_sync(0xffffffffu, m, o));

        // pass 2: staged weights + paired gather
        for (int b = start; b < end; b += 32) {
            int j = b + lane;
            bool v = j < end;
            int c = v ? col[j] : col[start];
            float a = v ? adj[j] : 0.f;
            float e = a * (sa1r + g_sa2[c]);
            e = e > 0.f ? e : 0.2f * e;
            float ex = v ? __expf(e - m) : 0.f;
            dsum += ex;
            wcp[lane] = make_float2(ex * g_vscale[c], __int_as_float(c));
            __syncwarp();
            int cnt8 = (min(32, end - b) + 7) & ~7;
            for (int t = 0; t < cnt8; t += 8)
                gather8_pair(wcp, t, half, sublane, accp);
            __syncwarp();
        }
    }

    // merge the two edge-halves: lane i + lane i+16 hold same cols
    #pragma unroll
    for (int i = 0; i < 8; i++)
        accp[i] += __shfl_xor_sync(0xffffffffu, accp[i], 16);

    #pragma unroll
    for (int o = 16; o; o >>= 1)
        dsum += __shfl_xor_sync(0xffffffffu, dsum, o);
    if (dsum <= 0.f) dsum = 1.0f;
    float inv = 1.0f / dsum;

    if (half == 0) {
        const float* bp = bias + (size_t)row * D_OUT + sublane * 8;
        float4 o0, o1;
        o0.x = accp[0] * inv + bp[0];
        o0.y = accp[1] * inv + bp[1];
        o0.z = accp[2] * inv + bp[2];
        o0.w = accp[3] * inv + bp[3];
        o1.x = accp[4] * inv + bp[4];
        o1.y = accp[5] * inv + bp[5];
        o1.z = accp[6] * inv + bp[6];
        o1.w = accp[7] * inv + bp[7];
        float4* op = (float4*)(out + (size_t)row * D_OUT + sublane * 8);
        op[0] = o0;
        op[1] = o1;
    }
}

// ---------------- launch ----------------
extern "C" void kernel_launch(void* const* d_in, const int* in_sizes, int n_in,
                              void* d_out, int out_size) {
    const float* x        = (const float*)d_in[0];
    const float* adj_val  = (const float*)d_in[1];
    const float* W1       = (const float*)d_in[2];
    const float* w2       = (const float*)d_in[3];
    const float* b2       = (const float*)d_in[4];
    const float* w3       = (const float*)d_in[5];
    const float* b3       = (const float*)d_in[6];
    const float* kern     = (const float*)d_in[7];
    const float* bias     = (const float*)d_in[8];
    const int*   edge_row = (const int*)d_in[9];
    const int*   edge_col = (const int*)d_in[10];
    float* out = (float*)d_out;

    short* qval;
    cudaGetSymbolAddress((void**)&qval, g_qval);

    cudaFuncSetAttribute(mma_gemm, cudaFuncAttributeMaxDynamicSharedMemorySize, SMEM_BYTES);

    prep_kernel<<<(F_IN * D_OUT + 255) / 256, 256>>>(kern, W1, w2, w3);
    rowptr_kernel<<<(E_EDGES + 1 + 255) / 256, 256>>>(edge_row);
    mma_gemm<<<(N_NODES + 127) / 128, 256, SMEM_BYTES>>>(x, qval, b2, b3, N_NODES);
    spmm_kernel<<<(N_NODES + 7) / 8, 256>>>(adj_val, edge_col, bias, out);
}

// round 9
// speedup vs baseline: 1.3529x; 1.2175x over previous
#include <cuda_runtime.h>
#include <cuda_fp16.h>
#include <math.h>
#include <stdint.h>

#define N_NODES 100000
#define E_EDGES 3200000
#define F_IN    256
#define D_OUT   128

// ---------------- static scratch (no cudaMalloc allowed) ----------------
__device__ float  g_u[F_IN];
__device__ float  g_v[F_IN];
__device__ float  g_sa1[N_NODES];
__device__ float2 g_sav[N_NODES];                    // .x = sa2, .y = vscale
__device__ int    g_rowptr[N_NODES + 1];
__device__ short  g_qval[(size_t)N_NODES * D_OUT];   // 25.6 MB int16 value
__device__ __half g_Bh[D_OUT * F_IN];                // 64 KB, [n][k] fp16

// ---------------- helpers ----------------
__device__ __forceinline__ void mma16816_f16(float* c, const uint32_t* a,
                                             uint32_t b0, uint32_t b1) {
    asm volatile(
        "mma.sync.aligned.m16n8k16.row.col.f32.f16.f16.f32 "
        "{%0,%1,%2,%3}, {%4,%5,%6,%7}, {%8,%9}, {%0,%1,%2,%3};"
        : "+f"(c[0]), "+f"(c[1]), "+f"(c[2]), "+f"(c[3])
        : "r"(a[0]), "r"(a[1]), "r"(a[2]), "r"(a[3]), "r"(b0), "r"(b1));
}

// ---------------- prep: uv (block 0) + B fp16 conversion ----------------
__global__ void prep_kernel(const float* __restrict__ kern,
                            const float* __restrict__ W1,
                            const float* __restrict__ w2,
                            const float* __restrict__ w3) {
    int idx = blockIdx.x * blockDim.x + threadIdx.x;
    if (idx < F_IN * D_OUT) {
        int k = idx >> 7;
        int n = idx & 127;
        g_Bh[n * F_IN + k] = __float2half_rn(kern[k * D_OUT + n]);
    }
    if (blockIdx.x == 0) {
        int t = threadIdx.x;
        float su = 0.f, sv = 0.f;
        #pragma unroll 8
        for (int d = 0; d < D_OUT; d++) {
            float w = W1[t * D_OUT + d];
            su += w * w2[d];
            sv += w * w3[d];
        }
        g_u[t] = su;
        g_v[t] = sv;
    }
}

// ---------------- row_ptr by boundary scatter ----------------
__global__ void rowptr_kernel(const int* __restrict__ er) {
    int j = blockIdx.x * blockDim.x + threadIdx.x;
    if (j > E_EDGES) return;
    int hi = (j == E_EDGES) ? N_NODES : er[j];
    int lo = (j == 0) ? -1 : er[j - 1];
    for (int i = lo + 1; i <= hi; i++) g_rowptr[i] = j;
}

// ---------------- fp16 HMMA GEMM (single term), 2 CTAs/SM ----------------
#define BPADW 132                          // B row stride in words (128 used)
#define APADW 20                           // A row stride per chunk in words (16 used)
#define ABUF_W 2560                        // 128 rows * 20 words
#define SM_B_W 0
#define SM_A_W (128 * BPADW)               // 16896
#define SM_U_W (SM_A_W + 2 * ABUF_W)       // 22016
#define SM_V_W (SM_U_W + 256)              // 22272
#define SMEM_WORDS (SM_V_W + 256)          // 22528
#define SMEM_BYTES (SMEM_WORDS * 4)        // 90112 B
#define CPADW 132
#define SM_PMAX_W SM_A_W                   // A buffers dead after k-loop

__global__ void __launch_bounds__(256, 2)
mma_gemm(const float* __restrict__ A, short* __restrict__ Q,
         const float* __restrict__ b2, const float* __restrict__ b3, int M) {
    extern __shared__ uint32_t sm[];
    int tid = threadIdx.x;

    // preload B (fp16, padded) and u/v
    {
        const uint4* bh = (const uint4*)g_Bh;
        #pragma unroll
        for (int r = 0; r < 16; r++) {
            int i = tid + r * 256;            // 0..4095 uint4 (128 rows x 32 uint4)
            int n = i >> 5, w = i & 31;
            *(uint4*)(sm + SM_B_W + n * BPADW + w * 4) = bh[i];
        }
        sm[SM_U_W + tid] = ((const uint32_t*)g_u)[tid];
        sm[SM_V_W + tid] = ((const uint32_t*)g_v)[tid];
    }
    __syncthreads();

    const float* sU = (const float*)(sm + SM_U_W);
    const float* sV = (const float*)(sm + SM_V_W);

    int wid = tid >> 5, lane = tid & 31;
    int wr = wid >> 2, wc = wid & 3;       // warp grid 2 x 4
    int lg = lane >> 2, lq = lane & 3;
    long base = (long)blockIdx.x * 128;
    int nbase = wc * 32;
    int kq = lq * 2;

    int srow_g = tid >> 3;                 // 0..31
    int skk = (tid & 7) * 4;               // 0,4,...,28

    float acc[4][4][4];
    #pragma unroll
    for (int i = 0; i < 4; i++)
        #pragma unroll
        for (int j = 0; j < 4; j++)
            #pragma unroll
            for (int q = 0; q < 4; q++) acc[i][j][q] = 0.f;

    float s1[4] = {0.f, 0.f, 0.f, 0.f}, s2[4] = {0.f, 0.f, 0.f, 0.f};
    float4 areg[4];

    auto load_chunk = [&](int k0) {
        #pragma unroll
        for (int it = 0; it < 4; ++it) {
            int row = it * 32 + srow_g;
            long grow = base + row;
            if (grow >= M) grow = M - 1;
            areg[it] = *(const float4*)(A + grow * F_IN + k0 + skk);
        }
    };
    auto store_chunk = [&](int k0, int bb) {
        uint32_t* ab = sm + SM_A_W + bb * ABUF_W;
        float u0 = sU[k0 + skk], u1 = sU[k0 + skk + 1],
              u2 = sU[k0 + skk + 2], u3 = sU[k0 + skk + 3];
        float v0 = sV[k0 + skk], v1 = sV[k0 + skk + 1],
              v2 = sV[k0 + skk + 2], v3 = sV[k0 + skk + 3];
        #pragma unroll
        for (int it = 0; it < 4; ++it) {
            int row = it * 32 + srow_g;
            float4 a = areg[it];
            s1[it] += a.x * u0 + a.y * u1 + a.z * u2 + a.w * u3;
            s2[it] += a.x * v0 + a.y * v1 + a.z * v2 + a.w * v3;
            __half2 h0 = __floats2half2_rn(a.x, a.y);
            __half2 h1 = __floats2half2_rn(a.z, a.w);
            *(uint2*)(ab + row * APADW + (skk >> 1)) =
                make_uint2(*(uint32_t*)&h0, *(uint32_t*)&h1);
        }
    };

    load_chunk(0);
    store_chunk(0, 0);
    __syncthreads();

    #pragma unroll 1
    for (int c = 0; c < 8; ++c) {
        if (c < 7) load_chunk((c + 1) * 32);   // LDGs in flight during MMA

        const uint32_t* ab = sm + SM_A_W + (c & 1) * ABUF_W;
        #pragma unroll
        for (int ksi = 0; ksi < 2; ++ksi) {
            uint32_t af[4][4];
            #pragma unroll
            for (int mt = 0; mt < 4; mt++) {
                int r0 = wr * 64 + mt * 16 + lg;
                int w0 = r0 * APADW + ksi * 8 + lq;
                int w1 = (r0 + 8) * APADW + ksi * 8 + lq;
                af[mt][0] = ab[w0];
                af[mt][1] = ab[w1];
                af[mt][2] = ab[w0 + 4];
                af[mt][3] = ab[w1 + 4];
            }
            uint32_t b0[4], b1[4];
            int kw = c * 16 + ksi * 8;         // word offset along K
            #pragma unroll
            for (int nt = 0; nt < 4; nt++) {
                int n0 = nbase + nt * 8 + lg;
                uint32_t off = (uint32_t)n0 * BPADW + (uint32_t)(kw + lq);
                b0[nt] = sm[SM_B_W + off];
                b1[nt] = sm[SM_B_W + off + 4];
            }
            #pragma unroll
            for (int mt = 0; mt < 4; mt++)
                #pragma unroll
                for (int nt = 0; nt < 4; nt++)
                    mma16816_f16(acc[mt][nt], af[mt], b0[nt], b1[nt]);
        }

        if (c < 7) store_chunk((c + 1) * 32, (c + 1) & 1);
        __syncthreads();
    }

    // sa reduce over the 8 staging threads per row
    {
        float bb2 = b2[0], bb3 = b3[0];
        #pragma unroll
        for (int it = 0; it < 4; ++it) {
            float a1 = s1[it], a2 = s2[it];
            #pragma unroll
            for (int o = 4; o; o >>= 1) {
                a1 += __shfl_xor_sync(0xffffffffu, a1, o);
                a2 += __shfl_xor_sync(0xffffffffu, a2, o);
            }
            if ((tid & 7) == 0) {
                long grow = base + it * 32 + srow_g;
                if (grow < M) {
                    g_sa1[grow] = a1 + bb2;
                    g_sav[grow].x = a2 + bb3;
                }
            }
        }
    }

    // epilogue: dump acc to smem fp32 (reuse B region)
    float* cs = (float*)sm;
    #pragma unroll
    for (int mt = 0; mt < 4; mt++) {
        int r0 = wr * 64 + mt * 16 + lg;
        #pragma unroll
        for (int nt = 0; nt < 4; nt++) {
            int col = nbase + nt * 8 + kq;
            *(float2*)(cs + r0 * CPADW + col) =
                make_float2(acc[mt][nt][0], acc[mt][nt][1]);
            *(float2*)(cs + (r0 + 8) * CPADW + col) =
                make_float2(acc[mt][nt][2], acc[mt][nt][3]);
        }
    }
    __syncthreads();

    // per-row absmax (2 threads per row), scale, int16 quantize
    {
        int row = tid >> 1, half = tid & 1;
        const float* cr = cs + row * CPADW + half * 64;
        float mx = 0.f;
        #pragma unroll 16
        for (int j = 0; j < 64; j++) mx = fmaxf(mx, fabsf(cr[j]));
        ((float*)(sm + SM_PMAX_W))[tid] = mx;
        __syncthreads();
        float rmx = fmaxf(((float*)(sm + SM_PMAX_W))[row * 2],
                          ((float*)(sm + SM_PMAX_W))[row * 2 + 1]);
        rmx = fmaxf(rmx, 1e-30f);
        long grow = base + row;
        if (half == 0 && grow < M) g_sav[grow].y = rmx * (1.0f / 32767.0f);
        float inv = 32767.0f / rmx;
        if (grow < M) {
            uint4* dst = (uint4*)(Q + (grow << 7) + half * 64);
            #pragma unroll
            for (int b8 = 0; b8 < 8; b8++) {
                short sv[8];
                #pragma unroll
                for (int j = 0; j < 8; j++)
                    sv[j] = (short)__float2int_rn(cr[b8 * 8 + j] * inv);
                dst[b8] = *(uint4*)sv;
            }
        }
    }
}

// ---------------- fused softmax + SpMM: paired-edge LDG.128 gather ----------------
__device__ __forceinline__ void gather8_pair(const float2* __restrict__ wc, int t,
                                             int half, int sublane, float* accp) {
    int4 raw[4];
    float w[4];
    #pragma unroll
    for (int q = 0; q < 4; q++) {
        float2 e = wc[t + 2 * q + half];
        w[q] = e.x;
        int cj = __float_as_int(e.y);
        raw[q] = *(const int4*)(g_qval + ((size_t)cj << 7) + sublane * 8);
    }
    #pragma unroll
    for (int q = 0; q < 4; q++) {
        short2 p0 = *reinterpret_cast<short2*>(&raw[q].x);
        short2 p1 = *reinterpret_cast<short2*>(&raw[q].y);
        short2 p2 = *reinterpret_cast<short2*>(&raw[q].z);
        short2 p3 = *reinterpret_cast<short2*>(&raw[q].w);
        accp[0] += w[q] * (float)p0.x;
        accp[1] += w[q] * (float)p0.y;
        accp[2] += w[q] * (float)p1.x;
        accp[3] += w[q] * (float)p1.y;
        accp[4] += w[q] * (float)p2.x;
        accp[5] += w[q] * (float)p2.y;
        accp[6] += w[q] * (float)p3.x;
        accp[7] += w[q] * (float)p3.y;
    }
}

__global__ __launch_bounds__(256) void spmm_kernel(const float* __restrict__ adj,
                                                   const int* __restrict__ col,
                                                   const float* __restrict__ bias,
                                                   float* __restrict__ out) {
    __shared__ float2 s_wc[8][32];
    int warp = threadIdx.x >> 5, lane = threadIdx.x & 31;
    int row = blockIdx.x * 8 + warp;
    if (row >= N_NODES) return;

    int start = g_rowptr[row];
    int end   = g_rowptr[row + 1];
    int deg   = end - start;
    int half = lane >> 4, sublane = lane & 15;

    if (deg <= 0) {
        if (half == 0) {
            const float4* bp = (const float4*)(bias + (size_t)row * D_OUT + sublane * 8);
            float4* op = (float4*)(out + (size_t)row * D_OUT + sublane * 8);
            op[0] = bp[0];
            op[1] = bp[1];
        }
        return;
    }

    float sa1r = g_sa1[row];
    float accp[8];
    #pragma unroll
    for (int i = 0; i < 8; i++) accp[i] = 0.f;
    float dsum = 0.f;
    float2* wcp = s_wc[warp];

    if (deg <= 32) {
        // single-batch fast path: one float2 load gives sa2 AND vscale
        int j = start + lane;
        bool v = j < end;
        int c = v ? col[j] : col[start];
        float a = v ? adj[j] : 0.f;
        float2 sv = g_sav[c];
        float e = a * (sa1r + sv.x);
        e = e > 0.f ? e : 0.2f * e;
        float m = v ? e : -INFINITY;
        #pragma unroll
        for (int o = 16; o; o >>= 1)
            m = fmaxf(m, __shfl_xor_sync(0xffffffffu, m, o));
        float ex = v ? __expf(e - m) : 0.f;
        dsum = ex;
        wcp[lane] = make_float2(ex * sv.y, __int_as_float(c));
        __syncwarp();
        int cnt8 = (deg + 7) & ~7;
        for (int t = 0; t < cnt8; t += 8)
            gather8_pair(wcp, t, half, sublane, accp);
    } else {
        // pass 1: segment max
        float m = -INFINITY;
        for (int j = start + lane; j < end; j += 32) {
            float a = adj[j];
            int   c = col[j];
            float e = a * (sa1r + g_sav[c].x);
            e = e > 0.f ? e : 0.2f * e;
            m = fmaxf(m, e);
        }
        #pragma unroll
        for (int o = 16; o; o >>= 1)
            m = fmaxf(m, __shfl_xor_sync(0xffffffffu, m, o));

        // pass 2: staged weights + paired gather
        for (int b = start; b < end; b += 32) {
            int j = b + lane;
            bool v = j < end;
            int c = v ? col[j] : col[start];
            float a = v ? adj[j] : 0.f;
            float2 sv = g_sav[c];
            float e = a * (sa1r + sv.x);
            e = e > 0.f ? e : 0.2f * e;
            float ex = v ? __expf(e - m) : 0.f;
            dsum += ex;
            wcp[lane] = make_float2(ex * sv.y, __int_as_float(c));
            __syncwarp();
            int cnt8 = (min(32, end - b) + 7) & ~7;
            for (int t = 0; t < cnt8; t += 8)
                gather8_pair(wcp, t, half, sublane, accp);
            __syncwarp();
        }
    }

    // merge the two edge-halves
    #pragma unroll
    for (int i = 0; i < 8; i++)
        accp[i] += __shfl_xor_sync(0xffffffffu, accp[i], 16);

    #pragma unroll
    for (int o = 16; o; o >>= 1)
        dsum += __shfl_xor_sync(0xffffffffu, dsum, o);
    if (dsum <= 0.f) dsum = 1.0f;
    float inv = 1.0f / dsum;

    if (half == 0) {
        const float* bp = bias + (size_t)row * D_OUT + sublane * 8;
        float4 o0, o1;
        o0.x = accp[0] * inv + bp[0];
        o0.y = accp[1] * inv + bp[1];
        o0.z = accp[2] * inv + bp[2];
        o0.w = accp[3] * inv + bp[3];
        o1.x = accp[4] * inv + bp[4];
        o1.y = accp[5] * inv + bp[5];
        o1.z = accp[6] * inv + bp[6];
        o1.w = accp[7] * inv + bp[7];
        float4* op = (float4*)(out + (size_t)row * D_OUT + sublane * 8);
        op[0] = o0;
        op[1] = o1;
    }
}

// ---------------- launch ----------------
extern "C" void kernel_launch(void* const* d_in, const int* in_sizes, int n_in,
                              void* d_out, int out_size) {
    const float* x        = (const float*)d_in[0];
    const float* adj_val  = (const float*)d_in[1];
    const float* W1       = (const float*)d_in[2];
    const float* w2       = (const float*)d_in[3];
    const float* b2       = (const float*)d_in[4];
    const float* w3       = (const float*)d_in[5];
    const float* b3       = (const float*)d_in[6];
    const float* kern     = (const float*)d_in[7];
    const float* bias     = (const float*)d_in[8];
    const int*   edge_row = (const int*)d_in[9];
    const int*   edge_col = (const int*)d_in[10];
    float* out = (float*)d_out;

    short* qval;
    cudaGetSymbolAddress((void**)&qval, g_qval);

    cudaFuncSetAttribute(mma_gemm, cudaFuncAttributeMaxDynamicSharedMemorySize, SMEM_BYTES);

    prep_kernel<<<(F_IN * D_OUT + 255) / 256, 256>>>(kern, W1, w2, w3);
    rowptr_kernel<<<(E_EDGES + 1 + 255) / 256, 256>>>(edge_row);
    mma_gemm<<<(N_NODES + 127) / 128, 256, SMEM_BYTES>>>(x, qval, b2, b3, N_NODES);
    spmm_kernel<<<(N_NODES + 7) / 8, 256>>>(adj_val, edge_col, bias, out);
}

// round 11
// speedup vs baseline: 1.4850x; 1.0976x over previous
#include <cuda_runtime.h>
#include <cuda_fp16.h>
#include <math.h>
#include <stdint.h>

#define N_NODES 100000
#define E_EDGES 3200000
#define F_IN    256
#define D_OUT   128

// ---------------- static scratch (no cudaMalloc allowed) ----------------
__device__ float  g_u[F_IN];
__device__ float  g_v[F_IN];
__device__ float  g_sa1[N_NODES];
__device__ float2 g_sav[N_NODES];                    // .x = sa2, .y = vscale
__device__ int    g_rowptr[N_NODES + 1];
__device__ unsigned short g_qval[(size_t)N_NODES * D_OUT]; // biased-u16 value
__device__ __half g_Bh[D_OUT * F_IN];                // 64 KB, [n][k] fp16

// ---------------- helpers ----------------
__device__ __forceinline__ void mma16816_f16(float* c, const uint32_t* a,
                                             uint32_t b0, uint32_t b1) {
    asm volatile(
        "mma.sync.aligned.m16n8k16.row.col.f32.f16.f16.f32 "
        "{%0,%1,%2,%3}, {%4,%5,%6,%7}, {%8,%9}, {%0,%1,%2,%3};"
        : "+f"(c[0]), "+f"(c[1]), "+f"(c[2]), "+f"(c[3])
        : "r"(a[0]), "r"(a[1]), "r"(a[2]), "r"(a[3]), "r"(b0), "r"(b1));
}

// ---------------- prep: uv (block 0) + B fp16 conversion ----------------
__global__ void prep_kernel(const float* __restrict__ kern,
                            const float* __restrict__ W1,
                            const float* __restrict__ w2,
                            const float* __restrict__ w3) {
    int idx = blockIdx.x * blockDim.x + threadIdx.x;
    if (idx < F_IN * D_OUT) {
        int k = idx >> 7;
        int n = idx & 127;
        g_Bh[n * F_IN + k] = __float2half_rn(kern[k * D_OUT + n]);
    }
    if (blockIdx.x == 0) {
        int t = threadIdx.x;
        float su = 0.f, sv = 0.f;
        #pragma unroll 8
        for (int d = 0; d < D_OUT; d++) {
            float w = W1[t * D_OUT + d];
            su += w * w2[d];
            sv += w * w3[d];
        }
        g_u[t] = su;
        g_v[t] = sv;
    }
}

// ---------------- row_ptr by boundary scatter ----------------
__global__ void rowptr_kernel(const int* __restrict__ er) {
    int j = blockIdx.x * blockDim.x + threadIdx.x;
    if (j > E_EDGES) return;
    int hi = (j == E_EDGES) ? N_NODES : er[j];
    int lo = (j == 0) ? -1 : er[j - 1];
    for (int i = lo + 1; i <= hi; i++) g_rowptr[i] = j;
}

// ---------------- fp16 HMMA GEMM (single term), 2 CTAs/SM ----------------
#define BPADW 132
#define APADW 20
#define ABUF_W 2560
#define SM_B_W 0
#define SM_A_W (128 * BPADW)               // 16896
#define SM_U_W (SM_A_W + 2 * ABUF_W)       // 22016
#define SM_V_W (SM_U_W + 256)
#define SMEM_WORDS (SM_V_W + 256)          // 22528
#define SMEM_BYTES (SMEM_WORDS * 4)        // 90112 B
#define CPADW 132
#define SM_PMAX_W SM_A_W

__global__ void __launch_bounds__(256, 2)
mma_gemm(const float* __restrict__ A, unsigned short* __restrict__ Q,
         const float* __restrict__ b2, const float* __restrict__ b3, int M) {
    extern __shared__ uint32_t sm[];
    int tid = threadIdx.x;

    {
        const uint4* bh = (const uint4*)g_Bh;
        #pragma unroll
        for (int r = 0; r < 16; r++) {
            int i = tid + r * 256;
            int n = i >> 5, w = i & 31;
            *(uint4*)(sm + SM_B_W + n * BPADW + w * 4) = bh[i];
        }
        sm[SM_U_W + tid] = ((const uint32_t*)g_u)[tid];
        sm[SM_V_W + tid] = ((const uint32_t*)g_v)[tid];
    }
    __syncthreads();

    const float* sU = (const float*)(sm + SM_U_W);
    const float* sV = (const float*)(sm + SM_V_W);

    int wid = tid >> 5, lane = tid & 31;
    int wr = wid >> 2, wc = wid & 3;
    int lg = lane >> 2, lq = lane & 3;
    long base = (long)blockIdx.x * 128;
    int nbase = wc * 32;
    int kq = lq * 2;

    int srow_g = tid >> 3;
    int skk = (tid & 7) * 4;

    float acc[4][4][4];
    #pragma unroll
    for (int i = 0; i < 4; i++)
        #pragma unroll
        for (int j = 0; j < 4; j++)
            #pragma unroll
            for (int q = 0; q < 4; q++) acc[i][j][q] = 0.f;

    float s1[4] = {0.f, 0.f, 0.f, 0.f}, s2[4] = {0.f, 0.f, 0.f, 0.f};
    float4 areg[4];

    auto load_chunk = [&](int k0) {
        #pragma unroll
        for (int it = 0; it < 4; ++it) {
            int row = it * 32 + srow_g;
            long grow = base + row;
            if (grow >= M) grow = M - 1;
            areg[it] = *(const float4*)(A + grow * F_IN + k0 + skk);
        }
    };
    auto store_chunk = [&](int k0, int bb) {
        uint32_t* ab = sm + SM_A_W + bb * ABUF_W;
        float u0 = sU[k0 + skk], u1 = sU[k0 + skk + 1],
              u2 = sU[k0 + skk + 2], u3 = sU[k0 + skk + 3];
        float v0 = sV[k0 + skk], v1 = sV[k0 + skk + 1],
              v2 = sV[k0 + skk + 2], v3 = sV[k0 + skk + 3];
        #pragma unroll
        for (int it = 0; it < 4; ++it) {
            int row = it * 32 + srow_g;
            float4 a = areg[it];
            s1[it] += a.x * u0 + a.y * u1 + a.z * u2 + a.w * u3;
            s2[it] += a.x * v0 + a.y * v1 + a.z * v2 + a.w * v3;
            __half2 h0 = __floats2half2_rn(a.x, a.y);
            __half2 h1 = __floats2half2_rn(a.z, a.w);
            *(uint2*)(ab + row * APADW + (skk >> 1)) =
                make_uint2(*(uint32_t*)&h0, *(uint32_t*)&h1);
        }
    };

    load_chunk(0);
    store_chunk(0, 0);
    __syncthreads();

    #pragma unroll 1
    for (int c = 0; c < 8; ++c) {
        if (c < 7) load_chunk((c + 1) * 32);

        const uint32_t* ab = sm + SM_A_W + (c & 1) * ABUF_W;
        #pragma unroll
        for (int ksi = 0; ksi < 2; ++ksi) {
            uint32_t af[4][4];
            #pragma unroll
            for (int mt = 0; mt < 4; mt++) {
                int r0 = wr * 64 + mt * 16 + lg;
                int w0 = r0 * APADW + ksi * 8 + lq;
                int w1 = (r0 + 8) * APADW + ksi * 8 + lq;
                af[mt][0] = ab[w0];
                af[mt][1] = ab[w1];
                af[mt][2] = ab[w0 + 4];
                af[mt][3] = ab[w1 + 4];
            }
            uint32_t b0[4], b1[4];
            int kw = c * 16 + ksi * 8;
            #pragma unroll
            for (int nt = 0; nt < 4; nt++) {
                int n0 = nbase + nt * 8 + lg;
                uint32_t off = (uint32_t)n0 * BPADW + (uint32_t)(kw + lq);
                b0[nt] = sm[SM_B_W + off];
                b1[nt] = sm[SM_B_W + off + 4];
            }
            #pragma unroll
            for (int mt = 0; mt < 4; mt++)
                #pragma unroll
                for (int nt = 0; nt < 4; nt++)
                    mma16816_f16(acc[mt][nt], af[mt], b0[nt], b1[nt]);
        }

        if (c < 7) store_chunk((c + 1) * 32, (c + 1) & 1);
        __syncthreads();
    }

    // sa reduce over the 8 staging threads per row
    {
        float bb2 = b2[0], bb3 = b3[0];
        #pragma unroll
        for (int it = 0; it < 4; ++it) {
            float a1 = s1[it], a2 = s2[it];
            #pragma unroll
            for (int o = 4; o; o >>= 1) {
                a1 += __shfl_xor_sync(0xffffffffu, a1, o);
                a2 += __shfl_xor_sync(0xffffffffu, a2, o);
            }
            if ((tid & 7) == 0) {
                long grow = base + it * 32 + srow_g;
                if (grow < M) {
                    g_sa1[grow] = a1 + bb2;
                    g_sav[grow].x = a2 + bb3;
                }
            }
        }
    }

    // epilogue: dump acc to smem fp32 (reuse B region)
    float* cs = (float*)sm;
    #pragma unroll
    for (int mt = 0; mt < 4; mt++) {
        int r0 = wr * 64 + mt * 16 + lg;
        #pragma unroll
        for (int nt = 0; nt < 4; nt++) {
            int col = nbase + nt * 8 + kq;
            *(float2*)(cs + r0 * CPADW + col) =
                make_float2(acc[mt][nt][0], acc[mt][nt][1]);
            *(float2*)(cs + (r0 + 8) * CPADW + col) =
                make_float2(acc[mt][nt][2], acc[mt][nt][3]);
        }
    }
    __syncthreads();

    // per-row absmax, scale, biased-u16 quantize (8 uint4 stores per half!)
    {
        int row = tid >> 1, half = tid & 1;
        const float* cr = cs + row * CPADW + half * 64;
        float mx = 0.f;
        #pragma unroll 16
        for (int j = 0; j < 64; j++) mx = fmaxf(mx, fabsf(cr[j]));
        ((float*)(sm + SM_PMAX_W))[tid] = mx;
        __syncthreads();
        float rmx = fmaxf(((float*)(sm + SM_PMAX_W))[row * 2],
                          ((float*)(sm + SM_PMAX_W))[row * 2 + 1]);
        rmx = fmaxf(rmx, 1e-30f);
        long grow = base + row;
        if (half == 0 && grow < M) g_sav[grow].y = rmx * (1.0f / 32767.0f);
        float inv = 32767.0f / rmx;
        if (grow < M) {
            uint4* dst = (uint4*)(Q + (grow << 7) + half * 64);
            #pragma unroll
            for (int b8 = 0; b8 < 8; b8++) {
                unsigned short sv[8];
                #pragma unroll
                for (int j = 0; j < 8; j++)
                    sv[j] = (unsigned short)(__float2int_rn(cr[b8 * 8 + j] * inv) + 32768);
                dst[b8] = *(uint4*)sv;   // 8 u16 = 16 B; 8 stores cover 64 values
            }
        }
    }
}

// ---------------- fused softmax + SpMM: single pass, PRMT decode ----------------
// value[c][col] = s_c * (f - 8421376) with f = as_float(0x4B000000 | u16).
__device__ __forceinline__ void gather8(const float2* __restrict__ wc, int t,
                                        int half, int sublane, float* accp) {
    uint4 raw[4];
    float w[4];
    #pragma unroll
    for (int q = 0; q < 4; q++) {
        float2 e = wc[t + 2 * q + half];
        w[q] = e.x;
        int cj = __float_as_int(e.y);
        raw[q] = *(const uint4*)(g_qval + ((size_t)cj << 7) + sublane * 8);
    }
    float wi = (w[0] + w[1]) + (w[2] + w[3]);
    #pragma unroll
    for (int q = 0; q < 4; q++) {
        uint32_t u[4] = {raw[q].x, raw[q].y, raw[q].z, raw[q].w};
        #pragma unroll
        for (int k = 0; k < 4; k++) {
            float f0 = __uint_as_float(__byte_perm(u[k], 0x4B000000u, 0x7410));
            float f1 = __uint_as_float(__byte_perm(u[k], 0x4B000000u, 0x7432));
            accp[2 * k]     += w[q] * f0;
            accp[2 * k + 1] += w[q] * f1;
        }
    }
    #pragma unroll
    for (int i = 0; i < 8; i++)
        accp[i] = fmaf(wi, -8421376.0f, accp[i]);
}

__global__ __launch_bounds__(256) void spmm_kernel(const float* __restrict__ adj,
                                                   const int* __restrict__ col,
                                                   const float* __restrict__ bias,
                                                   float* __restrict__ out) {
    __shared__ float2 s_wc[8][32];
    int warp = threadIdx.x >> 5, lane = threadIdx.x & 31;
    int row = blockIdx.x * 8 + warp;
    if (row >= N_NODES) return;

    int start = g_rowptr[row];
    int end   = g_rowptr[row + 1];
    int deg   = end - start;
    int half = lane >> 4, sublane = lane & 15;

    if (deg <= 0) {
        if (half == 0) {
            const float4* bp = (const float4*)(bias + (size_t)row * D_OUT + sublane * 8);
            float4* op = (float4*)(out + (size_t)row * D_OUT + sublane * 8);
            op[0] = bp[0];
            op[1] = bp[1];
        }
        return;
    }

    float sa1r = g_sa1[row];
    float accp[8];
    #pragma unroll
    for (int i = 0; i < 8; i++) accp[i] = 0.f;
    float dsum = 0.f;
    float2* wcp = s_wc[warp];

    // single pass: no max subtraction needed (|e| <= ~8, exp fp32-safe;
    // softmax is shift-invariant so result is identical)
    for (int b = start; b < end; b += 32) {
        int j = b + lane;
        bool v = j < end;
        int c = v ? col[j] : col[start];
        float a = v ? adj[j] : 0.f;
        float2 sv = g_sav[c];
        float e = a * (sa1r + sv.x);
        e = e > 0.f ? e : 0.2f * e;
        float ex = v ? __expf(e) : 0.f;
        dsum += ex;
        wcp[lane] = make_float2(ex * sv.y, __int_as_float(c));
        __syncwarp();
        int cnt8 = (min(32, end - b) + 7) & ~7;
        for (int t = 0; t < cnt8; t += 8)
            gather8(wcp, t, half, sublane, accp);
        __syncwarp();
    }

    // merge the two edge-halves
    #pragma unroll
    for (int i = 0; i < 8; i++)
        accp[i] += __shfl_xor_sync(0xffffffffu, accp[i], 16);

    #pragma unroll
    for (int o = 16; o; o >>= 1)
        dsum += __shfl_xor_sync(0xffffffffu, dsum, o);
    if (dsum <= 0.f) dsum = 1.0f;
    float inv = 1.0f / dsum;

    if (half == 0) {
        const float* bp = bias + (size_t)row * D_OUT + sublane * 8;
        float4 o0, o1;
        o0.x = accp[0] * inv + bp[0];
        o0.y = accp[1] * inv + bp[1];
        o0.z = accp[2] * inv + bp[2];
        o0.w = accp[3] * inv + bp[3];
        o1.x = accp[4] * inv + bp[4];
        o1.y = accp[5] * inv + bp[5];
        o1.z = accp[6] * inv + bp[6];
        o1.w = accp[7] * inv + bp[7];
        float4* op = (float4*)(out + (size_t)row * D_OUT + sublane * 8);
        op[0] = o0;
        op[1] = o1;
    }
}

// ---------------- launch ----------------
extern "C" void kernel_launch(void* const* d_in, const int* in_sizes, int n_in,
                              void* d_out, int out_size) {
    const float* x        = (const float*)d_in[0];
    const float* adj_val  = (const float*)d_in[1];
    const float* W1       = (const float*)d_in[2];
    const float* w2       = (const float*)d_in[3];
    const float* b2       = (const float*)d_in[4];
    const float* w3       = (const float*)d_in[5];
    const float* b3       = (const float*)d_in[6];
    const float* kern     = (const float*)d_in[7];
    const float* bias     = (const float*)d_in[8];
    const int*   edge_row = (const int*)d_in[9];
    const int*   edge_col = (const int*)d_in[10];
    float* out = (float*)d_out;

    unsigned short* qval;
    cudaGetSymbolAddress((void**)&qval, g_qval);

    cudaFuncSetAttribute(mma_gemm, cudaFuncAttributeMaxDynamicSharedMemorySize, SMEM_BYTES);

    prep_kernel<<<(F_IN * D_OUT + 255) / 256, 256>>>(kern, W1, w2, w3);
    rowptr_kernel<<<(E_EDGES + 1 + 255) / 256, 256>>>(edge_row);
    mma_gemm<<<(N_NODES + 127) / 128, 256, SMEM_BYTES>>>(x, qval, b2, b3, N_NODES);
    spmm_kernel<<<(N_NODES + 7) / 8, 256>>>(adj_val, edge_col, bias, out);
}